// round 8
// baseline (speedup 1.0000x reference)
#include <cuda_runtime.h>
#include <cuda_fp16.h>
#include <math.h>

#define NODES 100000
#define EDGES 1600000
#define SCAN_NB 98   // ceil(100000/1024)

typedef unsigned long long ull;

// ---------------- scratch (device globals: allocation-free) ----------------
__device__ int     g_deg[NODES];
__device__ int     g_fill[NODES];
__device__ int     g_ptr[NODES + 1];
__device__ int     g_aggpub[SCAN_NB];
__device__ int     g_csr[EDGES];
__device__ float   g_inv[NODES];
__device__ float   g_h0[NODES * 64];
__device__ float   g_h1[NODES * 64];
__device__ float   g_agg[NODES * 64];
__device__ __half2 g_hh0[NODES * 32];
__device__ __half2 g_hh1[NODES * 32];

// ---------------- packed f32x2 FMA (FFMA2 — only reachable via PTX) --------
__device__ __forceinline__ ull fma2(ull a, ull b, ull c) {
    ull d;
    asm("fma.rn.f32x2 %0, %1, %2, %3;" : "=l"(d) : "l"(a), "l"(b), "l"(c));
    return d;
}
__device__ __forceinline__ ull pack2(float x, float y) {
    float2 t = make_float2(x, y);
    return *(ull*)&t;
}
__device__ __forceinline__ float2 unpack2(ull v) { return *(float2*)&v; }

// ---------------- CSR build ----------------
__global__ void k_hist(const int* __restrict__ dst) {
    int e = blockIdx.x * blockDim.x + threadIdx.x;
    if (e < EDGES) atomicAdd(&g_deg[dst[e]], 1);
}

// single-pass scan: all 98 blocks resident; block b sums predecessors' aggregates
__global__ void k_scanlb() {
    __shared__ int sh[1024];
    __shared__ int spart[32];
    __shared__ int s_pref;
    int tid = threadIdx.x, b = blockIdx.x;
    int i = b * 1024 + tid;
    int v = (i < NODES) ? g_deg[i] : 0;
    sh[tid] = v;
    __syncthreads();
    for (int off = 1; off < 1024; off <<= 1) {
        int t = (tid >= off) ? sh[tid - off] : 0;
        __syncthreads();
        sh[tid] += t;
        __syncthreads();
    }
    if (tid == 1023) atomicExch(&g_aggpub[b], sh[1023]);   // publish aggregate

    int myv = 0;
    if (tid < b) {                                          // b <= 97 < 1024
        int t;
        do { t = atomicAdd(&g_aggpub[tid], 0); } while (t < 0);
        myv = t;
    }
#pragma unroll
    for (int off = 16; off; off >>= 1) myv += __shfl_xor_sync(0xffffffffu, myv, off);
    if ((tid & 31) == 0) spart[tid >> 5] = myv;
    __syncthreads();
    if (tid == 0) {
        int s = 0;
#pragma unroll
        for (int wdx = 0; wdx < 32; wdx++) s += spart[wdx];
        s_pref = s;
    }
    __syncthreads();
    if (i < NODES) {
        g_ptr[i] = s_pref + sh[tid] - v;                    // exclusive prefix
        g_inv[i] = (v > 0) ? (1.0f / (float)v) : 0.0f;
    }
    if (i == 0) g_ptr[NODES] = EDGES;
}

__global__ void k_fill(const int* __restrict__ src, const int* __restrict__ dst) {
    int e = blockIdx.x * blockDim.x + threadIdx.x;
    if (e < EDGES) {
        int d = dst[e];
        int pos = g_ptr[d] + atomicAdd(&g_fill[d], 1);
        g_csr[pos] = src[e];
    }
}

// ================= aggregation kernels: warp-per-node, max occupancy =======
// No smem, no syncthreads (warps retire independently), <=32 regs target.
__global__ void __launch_bounds__(256, 8) k_agg_f32(const float* __restrict__ hin,
                                                    float* __restrict__ aggout) {
    int node = blockIdx.x * 8 + (threadIdx.x >> 5);
    if (node >= NODES) return;
    int lane = threadIdx.x & 31;
    int beg = g_ptr[node], end = g_ptr[node + 1];
    float iv = g_inv[node];
    float sm = 0.f;
    int k = beg;
    for (; k + 7 < end; k += 8) {
        int id[8];
#pragma unroll
        for (int j = 0; j < 8; j++) id[j] = __ldg(&g_csr[k + j]);
        float vv[8];
#pragma unroll
        for (int j = 0; j < 8; j++) vv[j] = __ldg(&hin[id[j] * 32 + lane]);
#pragma unroll
        for (int j = 0; j < 8; j++) sm += vv[j];
    }
    for (; k < end; k++) sm += __ldg(&hin[__ldg(&g_csr[k]) * 32 + lane]);
    aggout[node * 32 + lane] = sm * iv;
}

__global__ void __launch_bounds__(256, 8) k_agg_f16(const __half2* __restrict__ hhin,
                                                    float2* __restrict__ aggout) {
    int node = blockIdx.x * 8 + (threadIdx.x >> 5);
    if (node >= NODES) return;
    int lane = threadIdx.x & 31;
    int beg = g_ptr[node], end = g_ptr[node + 1];
    float iv = g_inv[node];
    float sx = 0.f, sy = 0.f;
    int k = beg;
    for (; k + 7 < end; k += 8) {
        int id[8];
#pragma unroll
        for (int j = 0; j < 8; j++) id[j] = __ldg(&g_csr[k + j]);
        __half2 vv[8];
#pragma unroll
        for (int j = 0; j < 8; j++) vv[j] = __ldg(&hhin[id[j] * 32 + lane]);
#pragma unroll
        for (int j = 0; j < 8; j++) {
            float2 f = __half22float2(vv[j]);
            sx += f.x; sy += f.y;
        }
    }
    for (; k < end; k++) {
        float2 f = __half22float2(__ldg(&hhin[__ldg(&g_csr[k]) * 32 + lane]));
        sx += f.x; sy += f.y;
    }
    aggout[node * 32 + lane] = make_float2(sx * iv, sy * iv);
}

// ================= dense transform (FFMA2 GEMM) =================
// 64 nodes/block, 256 threads (8 warps x 8 nodes). agg read from global.
template <int DIN, bool RELU, bool PRED>
__global__ void __launch_bounds__(256) k_mm(const float* __restrict__ agg,
                                            const float* __restrict__ hin,
                                            const float* __restrict__ Wn,
                                            const float* __restrict__ bn,
                                            const float* __restrict__ Wr,
                                            const float* __restrict__ Wp1,
                                            const float* __restrict__ bp1,
                                            const float* __restrict__ Wp2,
                                            const float* __restrict__ bp2,
                                            float* __restrict__ hout,
                                            __half2* __restrict__ hhout,
                                            float* __restrict__ pred_out) {
    extern __shared__ ull dyn[];
    ull* sW0 = dyn;                  // [DIN*32] (Wn[i][2l],   Wr[i][2l])
    ull* sW1 = dyn + DIN * 32;       // [DIN*32] (Wn[i][2l+1], Wr[i][2l+1])
    ull* sAH = dyn + DIN * 64;       // [64*DIN] (agg, own) per [node][i]
    __shared__ float sV[64];

    int tid = threadIdx.x, w = tid >> 5, lane = tid & 31;
    int sb = w * 8;
    int n0 = blockIdx.x * 64;

    for (int idx = tid; idx < DIN * 32; idx += 256) {
        int i = idx >> 5, l = idx & 31;
        sW0[idx] = pack2(Wn[i * 64 + 2 * l],     Wr[i * 64 + 2 * l]);
        sW1[idx] = pack2(Wn[i * 64 + 2 * l + 1], Wr[i * 64 + 2 * l + 1]);
    }
    {
        const float* aggB = agg + (size_t)n0 * DIN;
        const float* hB   = hin + (size_t)n0 * DIN;
        int lim = min(64 * DIN, (NODES - n0) * DIN);
        for (int idx = tid; idx < lim; idx += 256)
            sAH[idx] = pack2(aggB[idx], hB[idx]);
    }
    __syncthreads();

    ull acc0[8], acc1[8];
#pragma unroll
    for (int s = 0; s < 8; s++) { acc0[s] = 0ull; acc1[s] = 0ull; }

#pragma unroll 4
    for (int i = 0; i < DIN; i++) {
        ull w0 = sW0[i * 32 + lane];
        ull w1 = sW1[i * 32 + lane];
#pragma unroll
        for (int s = 0; s < 8; s++) {
            ull ah = sAH[(sb + s) * DIN + i];   // broadcast LDS.64
            acc0[s] = fma2(ah, w0, acc0[s]);
            acc1[s] = fma2(ah, w1, acc1[s]);
        }
    }

    float2 b2 = ((const float2*)bn)[lane];
    float rx[8], ry[8];
#pragma unroll
    for (int s = 0; s < 8; s++) {
        float2 v0 = unpack2(acc0[s]);
        float2 v1 = unpack2(acc1[s]);
        rx[s] = v0.x + v0.y + b2.x;
        ry[s] = v1.x + v1.y + b2.y;
        if (RELU) { rx[s] = fmaxf(rx[s], 0.f); ry[s] = fmaxf(ry[s], 0.f); }
    }

    if (!PRED) {
#pragma unroll
        for (int s = 0; s < 8; s++) {
            int ng = n0 + sb + s;
            if (ng < NODES) {
                ((float2*)hout)[ng * 32 + lane] = make_float2(rx[s], ry[s]);
                hhout[ng * 32 + lane] = __floats2half2_rn(rx[s], ry[s]);
            }
        }
        return;
    }

    // ---- PRED: sigmoid(relu(h@Wp1+bp1)@Wp2 + bp2) ----
    __syncthreads();                       // all warps done with sW/sAH
    float*  sH  = (float*)sAH;             // [64][64]
    float2* sWp = (float2*)sW0;            // [64][32]

#pragma unroll
    for (int s = 0; s < 8; s++) {
        sH[(sb + s) * 64 + 2 * lane]     = rx[s];
        sH[(sb + s) * 64 + 2 * lane + 1] = ry[s];
    }
    const float2* Wp12 = (const float2*)Wp1;
    for (int idx = tid; idx < 64 * 32; idx += 256) sWp[idx] = Wp12[idx];
    if (tid < 64) sV[tid] = Wp2[tid];
    __syncthreads();

    float2 bb = ((const float2*)bp1)[lane];
    float  vb = bp2[0];
#pragma unroll 1
    for (int s = 0; s < 8; s++) {
        float ax = bb.x, ay = bb.y;
#pragma unroll 8
        for (int i = 0; i < 64; i++) {
            float hh = sH[(sb + s) * 64 + i];
            float2 wv = sWp[i * 32 + lane];
            ax += hh * wv.x;
            ay += hh * wv.y;
        }
        ax = fmaxf(ax, 0.f);
        ay = fmaxf(ay, 0.f);
        float z = ax * sV[2 * lane] + ay * sV[2 * lane + 1];
#pragma unroll
        for (int off = 16; off; off >>= 1) z += __shfl_xor_sync(0xffffffffu, z, off);
        int ng = n0 + sb + s;
        if (lane == 0 && ng < NODES) pred_out[ng] = 1.f / (1.f + expf(-(z + vb)));
    }
}

// ---------------- launch ----------------
extern "C" void kernel_launch(void* const* d_in, const int* in_sizes, int n_in,
                              void* d_out, int out_size) {
    const float* x   = (const float*)d_in[0];
    const int*   ei  = (const int*)d_in[1];
    const int*   src = ei;
    const int*   dst = ei + EDGES;
    const float* Wn0 = (const float*)d_in[2];
    const float* bn0 = (const float*)d_in[3];
    const float* Wr0 = (const float*)d_in[4];
    const float* Wn1 = (const float*)d_in[5];
    const float* bn1 = (const float*)d_in[6];
    const float* Wr1 = (const float*)d_in[7];
    const float* Wn2 = (const float*)d_in[8];
    const float* bn2 = (const float*)d_in[9];
    const float* Wr2 = (const float*)d_in[10];
    const float* Wp1 = (const float*)d_in[11];
    const float* bp1 = (const float*)d_in[12];
    const float* Wp2 = (const float*)d_in[13];
    const float* bp2 = (const float*)d_in[14];
    float* out = (float*)d_out;

    float *pH0, *pH1, *pAgg;
    __half2 *pHH0, *pHH1;
    int *pDeg, *pFill, *pAggpub;
    cudaGetSymbolAddress((void**)&pH0, g_h0);
    cudaGetSymbolAddress((void**)&pH1, g_h1);
    cudaGetSymbolAddress((void**)&pAgg, g_agg);
    cudaGetSymbolAddress((void**)&pHH0, g_hh0);
    cudaGetSymbolAddress((void**)&pHH1, g_hh1);
    cudaGetSymbolAddress((void**)&pDeg, g_deg);
    cudaGetSymbolAddress((void**)&pFill, g_fill);
    cudaGetSymbolAddress((void**)&pAggpub, g_aggpub);

    cudaFuncSetAttribute(k_mm<64, true,  false>,
                         cudaFuncAttributeMaxDynamicSharedMemorySize, 65536);
    cudaFuncSetAttribute(k_mm<64, false, true>,
                         cudaFuncAttributeMaxDynamicSharedMemorySize, 65536);

    cudaMemsetAsync(pDeg, 0, NODES * sizeof(int));
    cudaMemsetAsync(pFill, 0, NODES * sizeof(int));
    cudaMemsetAsync(pAggpub, 0xFF, SCAN_NB * sizeof(int));   // -1 sentinel

    // CSR build
    k_hist<<<(EDGES + 255) / 256, 256>>>(dst);
    k_scanlb<<<SCAN_NB, 1024>>>();
    k_fill<<<(EDGES + 255) / 256, 256>>>(src, dst);

    const int AGRID = (NODES + 7) / 8;     // 12500
    const int GGRID = (NODES + 63) / 64;   // 1563

    // layer 0: 32 -> 64, relu (fp32 gather of x)
    k_agg_f32<<<AGRID, 256>>>(x, pAgg);
    k_mm<32, true,  false><<<GGRID, 256, 32768>>>(pAgg, x, Wn0, bn0, Wr0,
            nullptr, nullptr, nullptr, nullptr, pH0, pHH0, nullptr);
    // layer 1: 64 -> 64, relu (fp16 gather)
    k_agg_f16<<<AGRID, 256>>>(pHH0, (float2*)pAgg);
    k_mm<64, true,  false><<<GGRID, 256, 65536>>>(pAgg, pH0, Wn1, bn1, Wr1,
            nullptr, nullptr, nullptr, nullptr, pH1, pHH1, nullptr);
    // layer 2: 64 -> 64, no relu, predictor fused
    k_agg_f16<<<AGRID, 256>>>(pHH1, (float2*)pAgg);
    k_mm<64, false, true ><<<GGRID, 256, 65536>>>(pAgg, pH1, Wn2, bn2, Wr2,
            Wp1, bp1, Wp2, bp2, nullptr, nullptr, out);

    (void)in_sizes; (void)n_in; (void)out_size;
}

// round 9
// speedup vs baseline: 1.2603x; 1.2603x over previous
#include <cuda_runtime.h>
#include <cuda_fp16.h>
#include <math.h>

#define NODES 100000
#define EDGES 1600000
#define SCAN_NB 98   // ceil(100000/1024)

typedef unsigned long long ull;

// ---------------- scratch (device globals: allocation-free) ----------------
__device__ int     g_deg[NODES];
__device__ int     g_fill[NODES];
__device__ int     g_ptr[NODES + 1];
__device__ int     g_aggpub[SCAN_NB];
__device__ int     g_csr[EDGES];
__device__ float   g_inv[NODES];
__device__ float   g_h0[NODES * 64];
__device__ float   g_h1[NODES * 64];
__device__ __half2 g_hx[NODES * 16];   // fp16 copy of x
__device__ __half2 g_hh0[NODES * 32];
__device__ __half2 g_hh1[NODES * 32];

// ---------------- packed f32x2 FMA (FFMA2 — only reachable via PTX) --------
__device__ __forceinline__ ull fma2(ull a, ull b, ull c) {
    ull d;
    asm("fma.rn.f32x2 %0, %1, %2, %3;" : "=l"(d) : "l"(a), "l"(b), "l"(c));
    return d;
}
__device__ __forceinline__ ull pack2(float x, float y) {
    float2 t = make_float2(x, y);
    return *(ull*)&t;
}
__device__ __forceinline__ float2 unpack2(ull v) { return *(float2*)&v; }

// ---------------- x -> fp16 ----------------
__global__ void k_cvt(const float2* __restrict__ x2, __half2* __restrict__ hx) {
    int i = blockIdx.x * blockDim.x + threadIdx.x;
    if (i < NODES * 16) {
        float2 v = x2[i];
        hx[i] = __floats2half2_rn(v.x, v.y);
    }
}

// ---------------- CSR build ----------------
__global__ void k_hist(const int* __restrict__ dst) {
    int e = blockIdx.x * blockDim.x + threadIdx.x;
    if (e < EDGES) atomicAdd(&g_deg[dst[e]], 1);
}

// single-pass scan: all 98 blocks resident; block b sums predecessors' aggregates
__global__ void k_scanlb() {
    __shared__ int sh[1024];
    __shared__ int spart[32];
    __shared__ int s_pref;
    int tid = threadIdx.x, b = blockIdx.x;
    int i = b * 1024 + tid;
    int v = (i < NODES) ? g_deg[i] : 0;
    sh[tid] = v;
    __syncthreads();
    for (int off = 1; off < 1024; off <<= 1) {
        int t = (tid >= off) ? sh[tid - off] : 0;
        __syncthreads();
        sh[tid] += t;
        __syncthreads();
    }
    if (tid == 1023) atomicExch(&g_aggpub[b], sh[1023]);   // publish aggregate

    int myv = 0;
    if (tid < b) {                                          // b <= 97 < 1024
        int t;
        do { t = atomicAdd(&g_aggpub[tid], 0); } while (t < 0);
        myv = t;
    }
#pragma unroll
    for (int off = 16; off; off >>= 1) myv += __shfl_xor_sync(0xffffffffu, myv, off);
    if ((tid & 31) == 0) spart[tid >> 5] = myv;
    __syncthreads();
    if (tid == 0) {
        int s = 0;
#pragma unroll
        for (int wdx = 0; wdx < 32; wdx++) s += spart[wdx];
        s_pref = s;
    }
    __syncthreads();
    if (i < NODES) {
        g_ptr[i] = s_pref + sh[tid] - v;                    // exclusive prefix
        g_inv[i] = (v > 0) ? (1.0f / (float)v) : 0.0f;
    }
    if (i == 0) g_ptr[NODES] = EDGES;
}

__global__ void k_fill(const int* __restrict__ src, const int* __restrict__ dst) {
    int e = blockIdx.x * blockDim.x + threadIdx.x;
    if (e < EDGES) {
        int d = dst[e];
        int pos = g_ptr[d] + atomicAdd(&g_fill[d], 1);
        g_csr[pos] = src[e];
    }
}

// ================= fused SAGE layer =================
// 512 threads, 16 warps x 8 nodes = 128 nodes/block.
// DIN=32: fp16 gather of x (64B rows, 2 edges per warp pass).
// DIN=64: fp16 gather (128B rows, warp per edge).
// GEMM via FFMA2, accumulator pair (sum a*Wn[f], sum h*Wr[f]). Own stays fp32.
template <int DIN, bool RELU, bool PRED>
__global__ void __launch_bounds__(512, 2) k_sage(const float* __restrict__ hin,
                                                 const __half2* __restrict__ hhin,
                                                 const float* __restrict__ Wn,
                                                 const float* __restrict__ bn,
                                                 const float* __restrict__ Wr,
                                                 const float* __restrict__ Wp1,
                                                 const float* __restrict__ bp1,
                                                 const float* __restrict__ Wp2,
                                                 const float* __restrict__ bp2,
                                                 float* __restrict__ hout,
                                                 __half2* __restrict__ hhout,
                                                 float* __restrict__ pred_out) {
    extern __shared__ ull dyn[];
    ull* sW0 = dyn;                  // [DIN*32] (Wn[i][2l],   Wr[i][2l])
    ull* sW1 = dyn + DIN * 32;       // [DIN*32] (Wn[i][2l+1], Wr[i][2l+1])
    ull* sAH = dyn + DIN * 64;       // [128*DIN] (agg, own) per [node][i]
    __shared__ float sV[64];

    int tid = threadIdx.x, w = tid >> 5, lane = tid & 31;
    int sb = w * 8;
    int n0 = blockIdx.x * 128;

    // ---- weights ----
    for (int idx = tid; idx < DIN * 32; idx += 512) {
        int i = idx >> 5, l = idx & 31;
        sW0[idx] = pack2(Wn[i * 64 + 2 * l],     Wr[i * 64 + 2 * l]);
        sW1[idx] = pack2(Wn[i * 64 + 2 * l + 1], Wr[i * 64 + 2 * l + 1]);
    }

    // ---- Phase A: aggregate 8 nodes per warp ----
#pragma unroll 1
    for (int s = 0; s < 8; s++) {
        int sl = sb + s;
        int ng = n0 + sl;
        if (ng >= NODES) break;
        int beg = g_ptr[ng], end = g_ptr[ng + 1];
        float iv = g_inv[ng];
        if (DIN == 64) {
            float sx = 0.f, sy = 0.f;
            int k = beg;
            for (; k + 7 < end; k += 8) {
                int id[8];
#pragma unroll
                for (int j = 0; j < 8; j++) id[j] = __ldg(&g_csr[k + j]);
                __half2 vv[8];
#pragma unroll
                for (int j = 0; j < 8; j++) vv[j] = __ldg(&hhin[id[j] * 32 + lane]);
#pragma unroll
                for (int j = 0; j < 8; j++) {
                    float2 f = __half22float2(vv[j]);
                    sx += f.x; sy += f.y;
                }
            }
            for (; k < end; k++) {
                float2 f = __half22float2(__ldg(&hhin[__ldg(&g_csr[k]) * 32 + lane]));
                sx += f.x; sy += f.y;
            }
            float2 own = ((const float2*)hin)[ng * 32 + lane];
            sAH[sl * 64 + 2 * lane]     = pack2(sx * iv, own.x);
            sAH[sl * 64 + 2 * lane + 1] = pack2(sy * iv, own.y);
        } else {   // DIN == 32: fp16 rows of 16 half2 (64B); two edges per pass
            int hl  = lane & 15;      // feature-pair index
            int sub = lane >> 4;      // edge subgroup 0/1
            float sx = 0.f, sy = 0.f;
            int k = beg + sub;
            for (; k + 14 < end; k += 16) {
                int id[8];
#pragma unroll
                for (int j = 0; j < 8; j++) id[j] = __ldg(&g_csr[k + 2 * j]);
                __half2 vv[8];
#pragma unroll
                for (int j = 0; j < 8; j++) vv[j] = __ldg(&hhin[id[j] * 16 + hl]);
#pragma unroll
                for (int j = 0; j < 8; j++) {
                    float2 f = __half22float2(vv[j]);
                    sx += f.x; sy += f.y;
                }
            }
            for (; k < end; k += 2) {
                float2 f = __half22float2(__ldg(&hhin[__ldg(&g_csr[k]) * 16 + hl]));
                sx += f.x; sy += f.y;
            }
            sx += __shfl_xor_sync(0xffffffffu, sx, 16);
            sy += __shfl_xor_sync(0xffffffffu, sy, 16);
            if (lane < 16) {
                float2 own = ((const float2*)hin)[ng * 16 + hl];
                sAH[sl * 32 + 2 * hl]     = pack2(sx * iv, own.x);
                sAH[sl * 32 + 2 * hl + 1] = pack2(sy * iv, own.y);
            }
        }
    }
    __syncthreads();

    // ---- Phase B: GEMM, lane owns output features (2*lane, 2*lane+1) ----
    ull acc0[8], acc1[8];
#pragma unroll
    for (int s = 0; s < 8; s++) { acc0[s] = 0ull; acc1[s] = 0ull; }

#pragma unroll 4
    for (int i = 0; i < DIN; i++) {
        ull w0 = sW0[i * 32 + lane];
        ull w1 = sW1[i * 32 + lane];
#pragma unroll
        for (int s = 0; s < 8; s++) {
            ull ah = sAH[(sb + s) * DIN + i];   // broadcast LDS.64
            acc0[s] = fma2(ah, w0, acc0[s]);
            acc1[s] = fma2(ah, w1, acc1[s]);
        }
    }

    float2 b2 = ((const float2*)bn)[lane];
    float rx[8], ry[8];
#pragma unroll
    for (int s = 0; s < 8; s++) {
        float2 v0 = unpack2(acc0[s]);
        float2 v1 = unpack2(acc1[s]);
        rx[s] = v0.x + v0.y + b2.x;
        ry[s] = v1.x + v1.y + b2.y;
        if (RELU) { rx[s] = fmaxf(rx[s], 0.f); ry[s] = fmaxf(ry[s], 0.f); }
    }

    if (!PRED) {
#pragma unroll
        for (int s = 0; s < 8; s++) {
            int ng = n0 + sb + s;
            if (ng < NODES) {
                ((float2*)hout)[ng * 32 + lane] = make_float2(rx[s], ry[s]);
                hhout[ng * 32 + lane] = __floats2half2_rn(rx[s], ry[s]);
            }
        }
        return;
    }

    // ---- PRED: sigmoid(relu(h@Wp1+bp1)@Wp2 + bp2) ----
    __syncthreads();                       // all warps done with sW/sAH
    float*  sH  = (float*)sAH;             // [128][64] = 32KB (of 64KB)
    float2* sWp = (float2*)sW0;            // [64][32]  = 16KB (of 32KB)

#pragma unroll
    for (int s = 0; s < 8; s++) {
        sH[(sb + s) * 64 + 2 * lane]     = rx[s];
        sH[(sb + s) * 64 + 2 * lane + 1] = ry[s];
    }
    const float2* Wp12 = (const float2*)Wp1;
    for (int idx = tid; idx < 64 * 32; idx += 512) sWp[idx] = Wp12[idx];
    if (tid < 64) sV[tid] = Wp2[tid];
    __syncthreads();

    float2 bb = ((const float2*)bp1)[lane];
    float  vb = bp2[0];
#pragma unroll 1
    for (int s = 0; s < 8; s++) {
        float ax = bb.x, ay = bb.y;
#pragma unroll 8
        for (int i = 0; i < 64; i++) {
            float hh = sH[(sb + s) * 64 + i];
            float2 wv = sWp[i * 32 + lane];
            ax += hh * wv.x;
            ay += hh * wv.y;
        }
        ax = fmaxf(ax, 0.f);
        ay = fmaxf(ay, 0.f);
        float z = ax * sV[2 * lane] + ay * sV[2 * lane + 1];
#pragma unroll
        for (int off = 16; off; off >>= 1) z += __shfl_xor_sync(0xffffffffu, z, off);
        int ng = n0 + sb + s;
        if (lane == 0 && ng < NODES) pred_out[ng] = 1.f / (1.f + expf(-(z + vb)));
    }
}

// ---------------- launch ----------------
extern "C" void kernel_launch(void* const* d_in, const int* in_sizes, int n_in,
                              void* d_out, int out_size) {
    const float* x   = (const float*)d_in[0];
    const int*   ei  = (const int*)d_in[1];
    const int*   src = ei;
    const int*   dst = ei + EDGES;
    const float* Wn0 = (const float*)d_in[2];
    const float* bn0 = (const float*)d_in[3];
    const float* Wr0 = (const float*)d_in[4];
    const float* Wn1 = (const float*)d_in[5];
    const float* bn1 = (const float*)d_in[6];
    const float* Wr1 = (const float*)d_in[7];
    const float* Wn2 = (const float*)d_in[8];
    const float* bn2 = (const float*)d_in[9];
    const float* Wr2 = (const float*)d_in[10];
    const float* Wp1 = (const float*)d_in[11];
    const float* bp1 = (const float*)d_in[12];
    const float* Wp2 = (const float*)d_in[13];
    const float* bp2 = (const float*)d_in[14];
    float* out = (float*)d_out;

    float *pH0, *pH1;
    __half2 *pHX, *pHH0, *pHH1;
    int *pDeg, *pFill, *pAggpub;
    cudaGetSymbolAddress((void**)&pH0, g_h0);
    cudaGetSymbolAddress((void**)&pH1, g_h1);
    cudaGetSymbolAddress((void**)&pHX, g_hx);
    cudaGetSymbolAddress((void**)&pHH0, g_hh0);
    cudaGetSymbolAddress((void**)&pHH1, g_hh1);
    cudaGetSymbolAddress((void**)&pDeg, g_deg);
    cudaGetSymbolAddress((void**)&pFill, g_fill);
    cudaGetSymbolAddress((void**)&pAggpub, g_aggpub);

    cudaFuncSetAttribute(k_sage<32, true,  false>,
                         cudaFuncAttributeMaxDynamicSharedMemorySize, 49152);
    cudaFuncSetAttribute(k_sage<64, true,  false>,
                         cudaFuncAttributeMaxDynamicSharedMemorySize, 98304);
    cudaFuncSetAttribute(k_sage<64, false, true>,
                         cudaFuncAttributeMaxDynamicSharedMemorySize, 98304);

    cudaMemsetAsync(pDeg, 0, NODES * sizeof(int));
    cudaMemsetAsync(pFill, 0, NODES * sizeof(int));
    cudaMemsetAsync(pAggpub, 0xFF, SCAN_NB * sizeof(int));   // -1 sentinel

    // x -> fp16 + CSR build
    k_cvt<<<(NODES * 16 + 255) / 256, 256>>>((const float2*)x, pHX);
    k_hist<<<(EDGES + 255) / 256, 256>>>(dst);
    k_scanlb<<<SCAN_NB, 1024>>>();
    k_fill<<<(EDGES + 255) / 256, 256>>>(src, dst);

    const int GRID = (NODES + 127) / 128;   // 782

    // layer 0: 32 -> 64, relu (fp16 gather of x, fp32 own)
    k_sage<32, true,  false><<<GRID, 512, 49152>>>(x, pHX, Wn0, bn0, Wr0,
            nullptr, nullptr, nullptr, nullptr, pH0, pHH0, nullptr);
    // layer 1: 64 -> 64, relu
    k_sage<64, true,  false><<<GRID, 512, 98304>>>(pH0, pHH0, Wn1, bn1, Wr1,
            nullptr, nullptr, nullptr, nullptr, pH1, pHH1, nullptr);
    // layer 2: 64 -> 64, no relu, predictor fused
    k_sage<64, false, true ><<<GRID, 512, 98304>>>(pH1, pHH1, Wn2, bn2, Wr2,
            Wp1, bp1, Wp2, bp2, nullptr, nullptr, out);

    (void)in_sizes; (void)n_in; (void)out_size;
}